// round 16
// baseline (speedup 1.0000x reference)
#include <cuda_runtime.h>

// CheapTrick liftering via 32x32 four-step FFT1024, one warp per frame.
// pack -> [regs: DFT32] -> twiddle -> smem transpose -> [regs: DFT32]
//   -> middle (untangle + lifter + re-tangle) entirely in registers via shuffles
//   -> [regs: IDFT32] -> twiddle -> smem transpose -> [regs: IDFT32] -> unpack.

#define BIN 1025
#define NTH 128
#define FPC 4            // frames per CTA (one warp each)
#define RS  33           // padded row stride in float2 (33 = conflict-free)

__device__ __forceinline__ float2 cmul(float2 a, float2 b) {
    return make_float2(a.x * b.x - a.y * b.y, a.x * b.y + a.y * b.x);
}

__device__ __forceinline__ int brev5(int j) {
    return ((j & 1) << 4) | ((j & 2) << 2) | (j & 4) | ((j & 8) >> 2) | ((j & 16) >> 4);
}

__device__ __forceinline__ float w32c(int j) {
    const float T[16] = {1.0f, 0.98078528f, 0.92387953f, 0.83146961f,
                         0.70710678f, 0.55557023f, 0.38268343f, 0.19509032f,
                         0.0f, -0.19509032f, -0.38268343f, -0.55557023f,
                         -0.70710678f, -0.83146961f, -0.92387953f, -0.98078528f};
    return T[j];
}
__device__ __forceinline__ float w32s(int j) {
    const float T[16] = {0.0f, 0.19509032f, 0.38268343f, 0.55557023f,
                         0.70710678f, 0.83146961f, 0.92387953f, 0.98078528f,
                         1.0f, 0.98078528f, 0.92387953f, 0.83146961f,
                         0.70710678f, 0.55557023f, 0.38268343f, 0.19509032f};
    return T[j];
}

// In-place radix-2 DIT; input must be in bit-reversed order; output natural.
template<bool INV>
__device__ __forceinline__ void fft32(float2* r) {
    #pragma unroll
    for (int s = 0; s < 5; s++) {
        const int half = 1 << s;
        #pragma unroll
        for (int i = 0; i < 32; i += 2 * half) {
            #pragma unroll
            for (int m = 0; m < half; m++) {
                const int tj = m << (4 - s);
                const float wc = w32c(tj);
                const float ws = INV ? w32s(tj) : -w32s(tj);
                float2 u = r[i + m];
                float2 v = r[i + m + half];
                float vr = v.x * wc - v.y * ws;
                float vi = v.x * ws + v.y * wc;
                r[i + m]        = make_float2(u.x + vr, u.y + vi);
                r[i + m + half] = make_float2(u.x - vr, u.y - vi);
            }
        }
    }
}

// One pair (klo, 1024-klo): untangle rfft2048.real -> lifter -> re-tangle.
// (c,s) = (cos,sin)(pi*klo/1024). liftA/liftB = sm*cp*inv1024 at klo / 1024-klo.
template<bool IS_A>
__device__ __forceinline__ float2 pair_update(float2 zown, float2 zpart,
                                              float c, float s,
                                              float liftA, float liftB) {
    float2 Za = IS_A ? zown : zpart;
    float2 Zb = IS_A ? zpart : zown;
    float sumr = Za.x + Zb.x, sumi = Za.y + Zb.y, difr = Za.x - Zb.x;
    float cepA = 0.5f * (sumr + c * sumi - s * difr);   // Re Y[klo]
    float cepB = 0.5f * (sumr - c * sumi + s * difr);   // Re Y[1024-klo]
    float SA = cepA * liftA;
    float SB = cepB * liftB;
    float mm = 0.5f * (SA + SB), dd = 0.5f * (SA - SB);
    return IS_A ? make_float2(mm - dd * s, dd * c)
                : make_float2(mm + dd * s, dd * c);
}

__device__ __forceinline__ int padi(int m) { return ((m >> 5) * RS) + (m & 31); }

__global__ __launch_bounds__(NTH) void cheaptrick_kernel(
    const float* __restrict__ x,
    const int*   __restrict__ f0,
    const float* __restrict__ sml,
    const float* __restrict__ cpl,
    float*       __restrict__ out,
    int frames)
{
    __shared__ float2 zbuf[FPC * RS * 32];

    const int lane = threadIdx.x & 31;
    const int wid  = threadIdx.x >> 5;
    const int frame = blockIdx.x * FPC + wid;
    if (frame >= frames) return;

    float2* zf = zbuf + wid * (RS * 32);
    const float* xr   = x   + (size_t)frame * BIN;
    float*       orow = out + (size_t)frame * BIN;
    const int f = f0[frame];
    const float* smr = sml + (size_t)f * BIN;
    const float* cpr = cpl + (size_t)f * BIN;
    const float inv = 1.0f / 1024.0f;

    // ---- pack: y = even extension of log(x); z[m] = y[2m] + i*y[2m+1] ----
    #pragma unroll
    for (int i = 0; i < 33; i++) {
        int n = i * 32 + lane;
        if (n <= 1024) {
            float Lv = __logf(xr[n]);
            int h = n >> 1;
            if ((n & 1) == 0) {
                zf[padi(h)].x = Lv;
                if (n >= 2 && n <= 1022) zf[padi(1024 - h)].x = Lv;
            } else {
                zf[padi(h)].y = Lv;
                zf[padi(1023 - h)].y = Lv;
            }
        }
    }
    __syncwarp();

    float2 r[32];

    // ---- forward step 1: thread b=lane, DFT32 over a of z[32a+b] ----
    #pragma unroll
    for (int j = 0; j < 32; j++) r[j] = zf[brev5(j) * RS + lane];
    fft32<false>(r);
    // twiddle W1024^{b*c} (incremental) and store row b
    {
        float sb, cb;
        __sincosf(-6.28318530717958647692f * (float)lane * (1.0f / 1024.0f), &sb, &cb);
        float2 wb = make_float2(cb, sb);
        float2 w  = make_float2(1.0f, 0.0f);
        #pragma unroll
        for (int cc = 0; cc < 32; cc++) {
            zf[lane * RS + cc] = cmul(r[cc], w);
            w = cmul(w, wb);
        }
    }
    __syncwarp();

    // ---- forward step 2: thread c=lane, DFT32 over b of G[b][c] -> X[c+32d] at reg d ----
    #pragma unroll
    for (int j = 0; j < 32; j++) r[j] = zf[brev5(j) * RS + lane];
    fft32<false>(r);

    // ---- middle: pairs (k, 1024-k) via shuffles; k = c + 32d ----
    {
        const int c = lane;
        const int pl = (32 - c) & 31;
        // incremental twiddles: angles pi*(c+32d)/1024 and pi*(32-c+32d)/1024, step pi/32
        const float stepc = 0.99518472667219688624f;   // cos(pi/32)
        const float steps = 0.09801714032956060199f;   // sin(pi/32)
        float cA, sA, cB, sB;
        __sincosf(3.14159265358979323846f * (float)c * (1.0f / 1024.0f), &sA, &cA);
        __sincosf(3.14159265358979323846f * (float)(32 - c) * (1.0f / 1024.0f), &sB, &cB);
        #pragma unroll
        for (int d = 0; d < 16; d++) {
            float2 pA, pB;
            pA.x = __shfl_sync(0xffffffffu, r[31 - d].x, pl);
            pA.y = __shfl_sync(0xffffffffu, r[31 - d].y, pl);
            pB.x = __shfl_sync(0xffffffffu, r[d].x, pl);
            pB.y = __shfl_sync(0xffffffffu, r[d].y, pl);
            if (c != 0) {
                int kA = c + 32 * d;                 // 1..511  -> A side
                float lA0 = smr[kA] * cpr[kA] * inv;
                float lA1 = smr[1024 - kA] * cpr[1024 - kA] * inv;
                r[d] = pair_update<true>(r[d], pA, cA, sA, lA0, lA1);
                int kB = 32 - c + 32 * d;            // partner-low of k = c+32(31-d)
                float lB0 = smr[kB] * cpr[kB] * inv;
                float lB1 = smr[1024 - kB] * cpr[1024 - kB] * inv;
                r[31 - d] = pair_update<false>(r[31 - d], pB, cB, sB, lB0, lB1);
            }
            // rotate both twiddles by pi/32
            float ncA = cA * stepc - sA * steps;
            sA = sA * stepc + cA * steps;  cA = ncA;
            float ncB = cB * stepc - sB * steps;
            sB = sB * stepc + cB * steps;  cB = ncB;
        }
        if (c == 0) {
            {   // k = 0 (with Y[1024] from Z[0])
                float2 Z0 = r[0];
                float cep0 = Z0.x + Z0.y;
                float cepN = Z0.x - Z0.y;
                float S0 = cep0 * smr[0]    * cpr[0]    * inv;
                float SN = cepN * smr[1024] * cpr[1024] * inv;
                r[0] = make_float2(0.5f * (S0 + SN), 0.5f * (S0 - SN));
            }
            {   // k = 512 (d = 16)
                float Sm = r[16].x * smr[512] * cpr[512] * inv;
                r[16] = make_float2(Sm, 0.0f);
            }
            float cS = 1.0f, sS = 0.0f;
            const float stc = 0.99518472667219688624f, sts = 0.09801714032956060199f;
            #pragma unroll
            for (int d = 1; d < 16; d++) {           // self pairs (32d, 1024-32d)
                float nc = cS * stc - sS * sts;      // advance to angle pi*32d/1024
                sS = sS * stc + cS * sts;  cS = nc;
                float2 a0 = r[d], b0 = r[32 - d];
                int klo = 32 * d;
                float l0 = smr[klo] * cpr[klo] * inv;
                float l1 = smr[1024 - klo] * cpr[1024 - klo] * inv;
                r[d]      = pair_update<true>(a0, b0, cS, sS, l0, l1);
                r[32 - d] = pair_update<false>(b0, a0, cS, sS, l0, l1);
            }
        }
    }

    // ---- inverse step 1: thread b=lane holds z2[32a+b] at reg a (same layout) ----
    #pragma unroll
    for (int j = 0; j < 32; j++) {           // in-place bit-reverse permutation
        int bj = brev5(j);
        if (j < bj) { float2 tmp = r[j]; r[j] = r[bj]; r[bj] = tmp; }
    }
    fft32<true>(r);
    {
        float sb, cb;
        __sincosf(6.28318530717958647692f * (float)lane * (1.0f / 1024.0f), &sb, &cb);
        float2 wb = make_float2(cb, sb);
        float2 w  = make_float2(1.0f, 0.0f);
        #pragma unroll
        for (int cc = 0; cc < 32; cc++) {
            zf[lane * RS + cc] = cmul(r[cc], w);
            w = cmul(w, wb);
        }
    }
    __syncwarp();

    // ---- inverse step 2: thread c=lane, IDFT32 over b -> x[c+32d] at reg d ----
    #pragma unroll
    for (int j = 0; j < 32; j++) r[j] = zf[brev5(j) * RS + lane];
    fft32<true>(r);
    #pragma unroll
    for (int d = 0; d < 32; d++) zf[d * RS + lane] = r[d];   // store pad(c+32d)
    __syncwarp();

    // ---- unpack: out[n] = y2[n] ----
    #pragma unroll
    for (int i = 0; i < 33; i++) {
        int n = i * 32 + lane;
        if (n <= 1024) {
            float2 v = zf[padi(n >> 1)];
            orow[n] = (n & 1) ? v.y : v.x;
        }
    }
}

extern "C" void kernel_launch(void* const* d_in, const int* in_sizes, int n_in,
                              void* d_out, int out_size) {
    const float* x  = (const float*)d_in[0];
    const int*   f0 = (const int*)d_in[1];
    const float* sm = (const float*)d_in[2];
    const float* cp = (const float*)d_in[3];
    float* out = (float*)d_out;
    const int frames = in_sizes[1];   // B*T
    cheaptrick_kernel<<<(frames + FPC - 1) / FPC, NTH>>>(x, f0, sm, cp, out, frames);
}

// round 17
// speedup vs baseline: 1.0781x; 1.0781x over previous
#include <cuda_runtime.h>

// CheapTrick liftering via 32x32 four-step FFT1024, one warp per frame.
// pack -> [regs: DFT32] -> twiddle -> smem transpose -> [regs: DFT32]
//   -> middle (untangle + lifter + re-tangle) entirely in registers via shuffles
//   -> [regs: IDFT32] -> twiddle -> smem transpose -> [regs: IDFT32] -> unpack.
// R16 post-mortem: plain __launch_bounds__(128) made ptxas budget 117 regs and
// spill r[32] to local memory (L1 81.5% busy, issue 7.6%, 3547us). The minBlocks=1
// hint below raises the register budget so the working set stays in registers.

#define BIN 1025
#define NTH 128
#define FPC 4            // frames per CTA (one warp each)
#define RS  33           // padded row stride in float2 (33 = 1 mod 16: conflict-free for 8B LDS)

__device__ __forceinline__ float2 cmul(float2 a, float2 b) {
    return make_float2(a.x * b.x - a.y * b.y, a.x * b.y + a.y * b.x);
}

__device__ __forceinline__ int brev5(int j) {
    return ((j & 1) << 4) | ((j & 2) << 2) | (j & 4) | ((j & 8) >> 2) | ((j & 16) >> 4);
}

__device__ __forceinline__ float w32c(int j) {
    const float T[16] = {1.0f, 0.98078528f, 0.92387953f, 0.83146961f,
                         0.70710678f, 0.55557023f, 0.38268343f, 0.19509032f,
                         0.0f, -0.19509032f, -0.38268343f, -0.55557023f,
                         -0.70710678f, -0.83146961f, -0.92387953f, -0.98078528f};
    return T[j];
}
__device__ __forceinline__ float w32s(int j) {
    const float T[16] = {0.0f, 0.19509032f, 0.38268343f, 0.55557023f,
                         0.70710678f, 0.83146961f, 0.92387953f, 0.98078528f,
                         1.0f, 0.98078528f, 0.92387953f, 0.83146961f,
                         0.70710678f, 0.55557023f, 0.38268343f, 0.19509032f};
    return T[j];
}

// In-place radix-2 DIT; input must be in bit-reversed order; output natural.
template<bool INV>
__device__ __forceinline__ void fft32(float2* r) {
    #pragma unroll
    for (int s = 0; s < 5; s++) {
        const int half = 1 << s;
        #pragma unroll
        for (int i = 0; i < 32; i += 2 * half) {
            #pragma unroll
            for (int m = 0; m < half; m++) {
                const int tj = m << (4 - s);
                const float wc = w32c(tj);
                const float ws = INV ? w32s(tj) : -w32s(tj);
                float2 u = r[i + m];
                float2 v = r[i + m + half];
                float vr = v.x * wc - v.y * ws;
                float vi = v.x * ws + v.y * wc;
                r[i + m]        = make_float2(u.x + vr, u.y + vi);
                r[i + m + half] = make_float2(u.x - vr, u.y - vi);
            }
        }
    }
}

// One pair (klo, 1024-klo): untangle rfft2048.real -> lifter -> re-tangle.
// (c,s) = (cos,sin)(pi*klo/1024). liftA/liftB = sm*cp*inv1024 at klo / 1024-klo.
template<bool IS_A>
__device__ __forceinline__ float2 pair_update(float2 zown, float2 zpart,
                                              float c, float s,
                                              float liftA, float liftB) {
    float2 Za = IS_A ? zown : zpart;
    float2 Zb = IS_A ? zpart : zown;
    float sumr = Za.x + Zb.x, sumi = Za.y + Zb.y, difr = Za.x - Zb.x;
    float cepA = 0.5f * (sumr + c * sumi - s * difr);   // Re Y[klo]
    float cepB = 0.5f * (sumr - c * sumi + s * difr);   // Re Y[1024-klo]
    float SA = cepA * liftA;
    float SB = cepB * liftB;
    float mm = 0.5f * (SA + SB), dd = 0.5f * (SA - SB);
    return IS_A ? make_float2(mm - dd * s, dd * c)
                : make_float2(mm + dd * s, dd * c);
}

__device__ __forceinline__ int padi(int m) { return ((m >> 5) * RS) + (m & 31); }

__global__ __launch_bounds__(NTH, 1) void cheaptrick_kernel(
    const float* __restrict__ x,
    const int*   __restrict__ f0,
    const float* __restrict__ sml,
    const float* __restrict__ cpl,
    float*       __restrict__ out,
    int frames)
{
    __shared__ float2 zbuf[FPC * RS * 32];

    const int lane = threadIdx.x & 31;
    const int wid  = threadIdx.x >> 5;
    const int frame = blockIdx.x * FPC + wid;
    if (frame >= frames) return;

    float2* zf = zbuf + wid * (RS * 32);
    const float* xr   = x   + (size_t)frame * BIN;
    float*       orow = out + (size_t)frame * BIN;
    const int f = f0[frame];
    const float* smr = sml + (size_t)f * BIN;
    const float* cpr = cpl + (size_t)f * BIN;
    const float inv = 1.0f / 1024.0f;

    // ---- pack: y = even extension of log(x); z[m] = y[2m] + i*y[2m+1] ----
    #pragma unroll
    for (int i = 0; i < 33; i++) {
        int n = i * 32 + lane;
        if (n <= 1024) {
            float Lv = __logf(xr[n]);
            int h = n >> 1;
            if ((n & 1) == 0) {
                zf[padi(h)].x = Lv;
                if (n >= 2 && n <= 1022) zf[padi(1024 - h)].x = Lv;
            } else {
                zf[padi(h)].y = Lv;
                zf[padi(1023 - h)].y = Lv;
            }
        }
    }
    __syncwarp();

    float2 r[32];

    // ---- forward step 1: thread b=lane, DFT32 over a of z[32a+b] ----
    #pragma unroll
    for (int j = 0; j < 32; j++) r[j] = zf[brev5(j) * RS + lane];
    fft32<false>(r);
    // twiddle W1024^{b*c} (incremental) and store row b
    {
        float sb, cb;
        __sincosf(-6.28318530717958647692f * (float)lane * (1.0f / 1024.0f), &sb, &cb);
        float2 wb = make_float2(cb, sb);
        float2 w  = make_float2(1.0f, 0.0f);
        #pragma unroll
        for (int cc = 0; cc < 32; cc++) {
            zf[lane * RS + cc] = cmul(r[cc], w);
            w = cmul(w, wb);
        }
    }
    __syncwarp();

    // ---- forward step 2: thread c=lane, DFT32 over b of G[b][c] -> X[c+32d] at reg d ----
    #pragma unroll
    for (int j = 0; j < 32; j++) r[j] = zf[brev5(j) * RS + lane];
    fft32<false>(r);

    // ---- middle: pairs (k, 1024-k) via shuffles; k = c + 32d ----
    {
        const int c = lane;
        const int pl = (32 - c) & 31;
        // incremental twiddles: angles pi*(c+32d)/1024 and pi*(32-c+32d)/1024, step pi/32
        const float stepc = 0.99518472667219688624f;   // cos(pi/32)
        const float steps = 0.09801714032956060199f;   // sin(pi/32)
        float cA, sA, cB, sB;
        __sincosf(3.14159265358979323846f * (float)c * (1.0f / 1024.0f), &sA, &cA);
        __sincosf(3.14159265358979323846f * (float)(32 - c) * (1.0f / 1024.0f), &sB, &cB);
        #pragma unroll
        for (int d = 0; d < 16; d++) {
            float2 pA, pB;
            pA.x = __shfl_sync(0xffffffffu, r[31 - d].x, pl);
            pA.y = __shfl_sync(0xffffffffu, r[31 - d].y, pl);
            pB.x = __shfl_sync(0xffffffffu, r[d].x, pl);
            pB.y = __shfl_sync(0xffffffffu, r[d].y, pl);
            if (c != 0) {
                int kA = c + 32 * d;                 // 1..511  -> A side
                float lA0 = smr[kA] * cpr[kA] * inv;
                float lA1 = smr[1024 - kA] * cpr[1024 - kA] * inv;
                r[d] = pair_update<true>(r[d], pA, cA, sA, lA0, lA1);
                int kB = 32 - c + 32 * d;            // partner-low of k = c+32(31-d)
                float lB0 = smr[kB] * cpr[kB] * inv;
                float lB1 = smr[1024 - kB] * cpr[1024 - kB] * inv;
                r[31 - d] = pair_update<false>(r[31 - d], pB, cB, sB, lB0, lB1);
            }
            // rotate both twiddles by pi/32
            float ncA = cA * stepc - sA * steps;
            sA = sA * stepc + cA * steps;  cA = ncA;
            float ncB = cB * stepc - sB * steps;
            sB = sB * stepc + cB * steps;  cB = ncB;
        }
        if (c == 0) {
            {   // k = 0 (with Y[1024] from Z[0])
                float2 Z0 = r[0];
                float cep0 = Z0.x + Z0.y;
                float cepN = Z0.x - Z0.y;
                float S0 = cep0 * smr[0]    * cpr[0]    * inv;
                float SN = cepN * smr[1024] * cpr[1024] * inv;
                r[0] = make_float2(0.5f * (S0 + SN), 0.5f * (S0 - SN));
            }
            {   // k = 512 (d = 16)
                float Sm = r[16].x * smr[512] * cpr[512] * inv;
                r[16] = make_float2(Sm, 0.0f);
            }
            float cS = 1.0f, sS = 0.0f;
            const float stc = 0.99518472667219688624f, sts = 0.09801714032956060199f;
            #pragma unroll
            for (int d = 1; d < 16; d++) {           // self pairs (32d, 1024-32d)
                float nc = cS * stc - sS * sts;      // advance to angle pi*32d/1024
                sS = sS * stc + cS * sts;  cS = nc;
                float2 a0 = r[d], b0 = r[32 - d];
                int klo = 32 * d;
                float l0 = smr[klo] * cpr[klo] * inv;
                float l1 = smr[1024 - klo] * cpr[1024 - klo] * inv;
                r[d]      = pair_update<true>(a0, b0, cS, sS, l0, l1);
                r[32 - d] = pair_update<false>(b0, a0, cS, sS, l0, l1);
            }
        }
    }

    // ---- inverse step 1: thread b=lane holds z2[32a+b] at reg a (same layout) ----
    #pragma unroll
    for (int j = 0; j < 32; j++) {           // in-place bit-reverse permutation
        int bj = brev5(j);
        if (j < bj) { float2 tmp = r[j]; r[j] = r[bj]; r[bj] = tmp; }
    }
    fft32<true>(r);
    {
        float sb, cb;
        __sincosf(6.28318530717958647692f * (float)lane * (1.0f / 1024.0f), &sb, &cb);
        float2 wb = make_float2(cb, sb);
        float2 w  = make_float2(1.0f, 0.0f);
        #pragma unroll
        for (int cc = 0; cc < 32; cc++) {
            zf[lane * RS + cc] = cmul(r[cc], w);
            w = cmul(w, wb);
        }
    }
    __syncwarp();

    // ---- inverse step 2: thread c=lane, IDFT32 over b -> x[c+32d] at reg d ----
    #pragma unroll
    for (int j = 0; j < 32; j++) r[j] = zf[brev5(j) * RS + lane];
    fft32<true>(r);
    #pragma unroll
    for (int d = 0; d < 32; d++) zf[d * RS + lane] = r[d];   // store pad(c+32d)
    __syncwarp();

    // ---- unpack: out[n] = y2[n] ----
    #pragma unroll
    for (int i = 0; i < 33; i++) {
        int n = i * 32 + lane;
        if (n <= 1024) {
            float2 v = zf[padi(n >> 1)];
            orow[n] = (n & 1) ? v.y : v.x;
        }
    }
}

extern "C" void kernel_launch(void* const* d_in, const int* in_sizes, int n_in,
                              void* d_out, int out_size) {
    const float* x  = (const float*)d_in[0];
    const int*   f0 = (const int*)d_in[1];
    const float* sm = (const float*)d_in[2];
    const float* cp = (const float*)d_in[3];
    float* out = (float*)d_out;
    const int frames = in_sizes[1];   // B*T
    cheaptrick_kernel<<<(frames + FPC - 1) / FPC, NTH>>>(x, f0, sm, cp, out, frames);
}